// round 2
// baseline (speedup 1.0000x reference)
#include <cuda_runtime.h>

// Depthwise causal conv1d, channel-last. x:(B,L,D) fp32; w:(K=4,1,D); b:(D,).
// y[b,l,d] = bias[d] + sum_k x[b,l+k-3,d]*w[k,d]
//
// HBM-bound streaming kernel. Round-2 strategy: eliminate wave quantization.
// Fine-grained items (CHUNK=8 along l), exactly 592 blocks (148 SM x 4 resident),
// grid-stride -> 1.2% tail instead of 16% two-wave tail. Halo reads (3/8) are
// L2 hits because concurrent blocks process adjacent l-chunks. Weights fixed
// per block (blockIdx.y selects d4 group). Streaming stores protect L2.

#define CHUNK 8
#define THREADS 256

__global__ void __launch_bounds__(THREADS, 4) dwconv_kernel(
    const float4* __restrict__ x,
    const float4* __restrict__ w,
    const float4* __restrict__ bias,
    float4* __restrict__ y,
    int L, int D4, int nlc, int nitems)
{
    const int d4 = blockIdx.y * THREADS + threadIdx.x;  // fixed channel group

    // K=4 weights + bias live in registers for the whole block lifetime
    const float4 w0 = w[0 * D4 + d4];
    const float4 w1 = w[1 * D4 + d4];
    const float4 w2 = w[2 * D4 + d4];
    const float4 w3 = w[3 * D4 + d4];
    const float4 bb = bias[d4];
    const float4 z4 = make_float4(0.f, 0.f, 0.f, 0.f);

    // grid-stride over fine items: item -> (b, l-chunk), lc fastest so that
    // concurrently-running blocks touch adjacent l (halo stays hot in L2)
    for (int item = blockIdx.x; item < nitems; item += gridDim.x) {
        const int lc = item % nlc;
        const int b  = item / nlc;
        const int l0 = lc * CHUNK;
        const int base = (b * L + l0) * D4 + d4;   // 32-bit: max ~8.4M floats4

        float4 h0, h1, h2;
        if (l0 >= 3) {
            h0 = x[base - 3 * D4];
            h1 = x[base - 2 * D4];
            h2 = x[base - 1 * D4];
        } else {  // l0 == 0 (CHUNK >= 3): causal zero padding
            h0 = z4; h1 = z4; h2 = z4;
        }

        #pragma unroll
        for (int i = 0; i < CHUNK; ++i) {
            const int idx = base + i * D4;
            const float4 xc = x[idx];
            float4 o;
            o.x = fmaf(w3.x, xc.x, fmaf(w2.x, h2.x, fmaf(w1.x, h1.x, fmaf(w0.x, h0.x, bb.x))));
            o.y = fmaf(w3.y, xc.y, fmaf(w2.y, h2.y, fmaf(w1.y, h1.y, fmaf(w0.y, h0.y, bb.y))));
            o.z = fmaf(w3.z, xc.z, fmaf(w2.z, h2.z, fmaf(w1.z, h1.z, fmaf(w0.z, h0.z, bb.z))));
            o.w = fmaf(w3.w, xc.w, fmaf(w2.w, h2.w, fmaf(w1.w, h1.w, fmaf(w0.w, h0.w, bb.w))));
            __stcs(&y[idx], o);   // streaming store: don't pollute L2
            h0 = h1; h1 = h2; h2 = xc;
        }
    }
}

extern "C" void kernel_launch(void* const* d_in, const int* in_sizes, int n_in,
                              void* d_out, int out_size)
{
    const float* x  = (const float*)d_in[0];
    const float* w  = (const float*)d_in[1];
    const float* bi = (const float*)d_in[2];
    float* y = (float*)d_out;

    const int D  = in_sizes[2];            // 2048
    const int BL = in_sizes[0] / D;        // B*L
    int L = 4096;
    if (BL % L != 0) L = BL;               // fallback for unexpected shapes
    const int B  = BL / L;
    const int D4 = D / 4;

    const int nlc    = L / CHUNK;          // l-chunks per sequence (512)
    const int nitems = B * nlc;            // items per d4-group (2048)

    const int ngroups = D4 / THREADS;      // 2 d4-groups of 256 threads
    // 148 SMs x 4 resident blocks = 592 total; split evenly across groups
    int gx = 592 / ngroups;
    if (gx < 1) gx = 1;
    if (gx > nitems) gx = nitems;

    dim3 grid(gx, ngroups, 1);
    dwconv_kernel<<<grid, THREADS>>>(
        (const float4*)x, (const float4*)w, (const float4*)bi,
        (float4*)y, L, D4, nlc, nitems);
}